// round 2
// baseline (speedup 1.0000x reference)
#include <cuda_runtime.h>

#define NB   2
#define C    64
#define H    128
#define WW   128
#define HW   (H*WW)
#define NH   4
#define DK   16
#define KS   5
#define K2   25

// Scratch (allocation-free rule: __device__ globals).
// qp/kp/vp/mid stored pixel-major: [n, h*w, c]  (channel contiguous -> coalesced gathers)
__device__ float g_qp [NB*HW*C];
__device__ float g_kp [NB*HW*C];
__device__ float g_vp [NB*HW*C];
__device__ float g_mid[NB*HW*C];

// ---------------------------------------------------------------------------
// Kernel 1: three 1x1 convs, input [n,c,h,w] -> output [n,h*w,c] (transposed)
// 256 threads = 64 pixels, each thread computes 16 output channels.
// smem: Ws (16KB) + sin_ (16.25KB, reused as transpose staging after compute)
// ---------------------------------------------------------------------------
__global__ void conv_in_kernel(const float* __restrict__ q,
                               const float* __restrict__ k,
                               const float* __restrict__ v,
                               const float* __restrict__ Wq,
                               const float* __restrict__ Wk,
                               const float* __restrict__ Wv)
{
    __shared__ float Ws[C*C];
    __shared__ float sin_[C*65];   // doubles as transpose-out buffer (64*65 <= C*65)

    const int which = blockIdx.y;
    const float* src = (which == 0) ? q  : (which == 1) ? k  : v;
    const float* Wsrc= (which == 0) ? Wq : (which == 1) ? Wk : Wv;
    float*       dst = (which == 0) ? g_qp : (which == 1) ? g_kp : g_vp;

    const int b       = blockIdx.x / (HW/64);
    const int pixBase = (blockIdx.x % (HW/64)) * 64;
    const int tid     = threadIdx.x;

    for (int i = tid; i < C*C; i += 256) Ws[i] = Wsrc[i];
    for (int i = tid; i < C*64; i += 256) {
        int c = i >> 6, p = i & 63;
        sin_[c*65 + p] = src[(b*C + c)*HW + pixBase + p];
    }
    __syncthreads();

    const int p  = tid & 63;
    const int og = tid >> 6;       // 4 groups x 16 outputs
    float acc[16];
    #pragma unroll
    for (int i = 0; i < 16; i++) acc[i] = 0.f;
    #pragma unroll
    for (int c = 0; c < C; c++) {
        float xv = sin_[c*65 + p];
        #pragma unroll
        for (int i = 0; i < 16; i++)
            acc[i] = fmaf(Ws[(og*16 + i)*C + c], xv, acc[i]);
    }
    __syncthreads();   // all reads of sin_ complete; reuse it as sout
    #pragma unroll
    for (int i = 0; i < 16; i++) sin_[p*65 + og*16 + i] = acc[i];
    __syncthreads();

    for (int i = tid; i < 64*C; i += 256)
        dst[(b*HW + pixBase)*C + i] = sin_[(i >> 6)*65 + (i & 63)];
}

// ---------------------------------------------------------------------------
// Kernel 2: flow-guided attention. Warp per pixel (8 pixels / 256-thread block).
// Lane l owns channels 2l, 2l+1; head = lane>>3. Online softmax over 25 taps,
// v gathered in the same loop reusing the corner weights of k.
// Writes g_mid ([n,hw,c]) and attn map ([n,nh,k2,h,w]) directly to d_out.
// ---------------------------------------------------------------------------
__global__ void attn_kernel(const float* __restrict__ flow,
                            float* __restrict__ attn_out)
{
    __shared__ float sLog[8][NH][K2];
    __shared__ float sM[8][NH];
    __shared__ float sSInv[8][NH];

    const int tid  = threadIdx.x;
    const int warp = tid >> 5;
    const int lane = tid & 31;

    const int b       = blockIdx.x / (HW/8);
    const int pixBase = (blockIdx.x % (HW/8)) * 8;
    const int pix     = pixBase + warp;
    const int y = pix >> 7;
    const int x = pix & 127;

    const float fx = flow[(b*2 + 0)*HW + pix];
    const float fy = flow[(b*2 + 1)*HW + pix];

    const float2* __restrict__ qp2 = (const float2*)g_qp;
    const float2* __restrict__ kp2 = (const float2*)g_kp;
    const float2* __restrict__ vp2 = (const float2*)g_vp;

    float2 qv = qp2[(b*HW + pix)*32 + lane];
    const float scale = 0.25f;              // 1/sqrt(dk=16)
    qv.x *= scale; qv.y *= scale;

    const int head = lane >> 3;

    float m = -1e30f, s = 0.f, ax = 0.f, ay = 0.f;

    #pragma unroll
    for (int kk = 0; kk < K2; kk++) {
        const int ky = kk/5 - 2, kx = kk%5 - 2;
        float gxf = (float)(x + kx) + fx;
        float gyf = (float)(y + ky) + fy;
        float fx0 = floorf(gxf), fy0 = floorf(gyf);
        int ix0 = (int)fx0, iy0 = (int)fy0;
        float wx1 = gxf - fx0, wy1 = gyf - fy0;
        float wx0 = 1.f - wx1, wy0 = 1.f - wy1;

        float kvx = 0.f, kvy = 0.f, vvx = 0.f, vvy = 0.f;
        #pragma unroll
        for (int cy = 0; cy < 2; cy++) {
            int iy = iy0 + cy;
            float wy = cy ? wy1 : wy0;
            bool okY = ((unsigned)iy < (unsigned)H);
            int iyc = min(max(iy, 0), H-1);
            #pragma unroll
            for (int cx = 0; cx < 2; cx++) {
                int ix = ix0 + cx;
                float wx = cx ? wx1 : wx0;
                float wc = (okY && (unsigned)ix < (unsigned)WW) ? wy*wx : 0.f;
                int ixc = min(max(ix, 0), WW-1);
                int off = (b*HW + iyc*WW + ixc)*32 + lane;
                float2 kv = __ldg(&kp2[off]);
                float2 vv = __ldg(&vp2[off]);
                kvx = fmaf(wc, kv.x, kvx);  kvy = fmaf(wc, kv.y, kvy);
                vvx = fmaf(wc, vv.x, vvx);  vvy = fmaf(wc, vv.y, vvy);
            }
        }

        float part = qv.x*kvx + qv.y*kvy;
        part += __shfl_xor_sync(0xffffffffu, part, 1);
        part += __shfl_xor_sync(0xffffffffu, part, 2);
        part += __shfl_xor_sync(0xffffffffu, part, 4);
        // part = logit for (head, kk), identical on all 8 lanes of the head

        if ((lane & 7) == 0) sLog[warp][head][kk] = part;

        float mn   = fmaxf(m, part);
        float corr = __expf(m - mn);
        float pw   = __expf(part - mn);
        s  = s*corr + pw;
        ax = ax*corr + pw*vvx;
        ay = ay*corr + pw*vvy;
        m  = mn;
    }

    const float inv = 1.f / s;
    ((float2*)g_mid)[(b*HW + pix)*32 + lane] = make_float2(ax*inv, ay*inv);

    if ((lane & 7) == 0) { sM[warp][head] = m; sSInv[warp][head] = inv; }
    __syncthreads();

    // attn map [n, nh, k2, h, w]; 4*25*8 = 800 values per block, pixel-fastest
    for (int i = tid; i < NH*K2*8; i += 256) {
        int pi = i & 7;
        int ht = i >> 3;
        int h = ht / K2, t = ht % K2;
        float val = __expf(sLog[pi][h][t] - sM[pi][h]) * sSInv[pi][h];
        attn_out[((b*NH + h)*K2 + t)*HW + pixBase + pi] = val;
    }
}

// ---------------------------------------------------------------------------
// Kernel 3: final 1x1 conv, g_mid [n,hw,c] -> out [n,c,h,w]
// ---------------------------------------------------------------------------
__global__ void conv_out_kernel(const float* __restrict__ Wfc,
                                float* __restrict__ out)
{
    __shared__ float Ws[C*C];
    __shared__ float sin_[C*65];

    const int b       = blockIdx.x / (HW/64);
    const int pixBase = (blockIdx.x % (HW/64)) * 64;
    const int tid     = threadIdx.x;

    for (int i = tid; i < C*C; i += 256) Ws[i] = Wfc[i];
    for (int i = tid; i < 64*C; i += 256) {
        int c = i & 63;
        sin_[c*65 + (i >> 6)] = g_mid[(b*HW + pixBase)*C + i];
    }
    __syncthreads();

    const int p  = tid & 63;
    const int og = tid >> 6;
    float acc[16];
    #pragma unroll
    for (int i = 0; i < 16; i++) acc[i] = 0.f;
    #pragma unroll
    for (int c = 0; c < C; c++) {
        float xv = sin_[c*65 + p];
        #pragma unroll
        for (int i = 0; i < 16; i++)
            acc[i] = fmaf(Ws[(og*16 + i)*C + c], xv, acc[i]);
    }
    #pragma unroll
    for (int i = 0; i < 16; i++)
        out[(b*C + og*16 + i)*HW + pixBase + p] = acc[i];
}

// ---------------------------------------------------------------------------
extern "C" void kernel_launch(void* const* d_in, const int* in_sizes, int n_in,
                              void* d_out, int out_size)
{
    const float* q    = (const float*)d_in[0];
    const float* k    = (const float*)d_in[1];
    const float* v    = (const float*)d_in[2];
    const float* flow = (const float*)d_in[3];
    const float* Wq   = (const float*)d_in[4];
    const float* Wk   = (const float*)d_in[5];
    const float* Wv   = (const float*)d_in[6];
    const float* Wfc  = (const float*)d_in[7];

    float* out  = (float*)d_out;              // [n, c, h, w]
    float* attn = out + NB*C*HW;              // [n, nh, k2, h, w]

    dim3 g1(NB*HW/64, 3);
    conv_in_kernel<<<g1, 256>>>(q, k, v, Wq, Wk, Wv);
    attn_kernel<<<NB*HW/8, 256>>>(flow, attn);
    conv_out_kernel<<<NB*HW/64, 256>>>(Wfc, out);
}

// round 3
// speedup vs baseline: 1.3790x; 1.3790x over previous
#include <cuda_runtime.h>

#define NB   2
#define C    64
#define H    128
#define WW   128
#define HW   (H*WW)
#define NH   4
#define DK   16
#define KS   5
#define K2   25

// Scratch (allocation-free rule: __device__ globals).
// qp/kp/vp/mid stored pixel-major: [n, h*w, c]  (channel contiguous -> coalesced gathers)
__device__ float g_qp [NB*HW*C];
__device__ float g_kp [NB*HW*C];
__device__ float g_vp [NB*HW*C];
__device__ float g_mid[NB*HW*C];

// ---------------------------------------------------------------------------
// Kernel 1: three 1x1 convs, [n,c,h,w] -> [n,h*w,c] (transposed), register-tiled.
// Block: 256 threads, tile 128 pixels x 64 outs. Thread: 4 pix x 8 outs.
// X staged in smem [c][pix] (conflict-free), W streamed from L1 (broadcast ldg).
// ---------------------------------------------------------------------------
__global__ __launch_bounds__(256) void conv_in_kernel(
    const float* __restrict__ q,
    const float* __restrict__ k,
    const float* __restrict__ v,
    const float* __restrict__ Wq,
    const float* __restrict__ Wk,
    const float* __restrict__ Wv)
{
    __shared__ float Xs[64*128];

    const int which = blockIdx.y;
    const float* src = (which == 0) ? q  : (which == 1) ? k  : v;
    const float* Wsrc= (which == 0) ? Wq : (which == 1) ? Wk : Wv;
    float*       dst = (which == 0) ? g_qp : (which == 1) ? g_kp : g_vp;

    const int b       = blockIdx.x / (HW/128);
    const int pixBase = (blockIdx.x % (HW/128)) * 128;
    const int tid     = threadIdx.x;

    // Stage X: 64 ch x 128 pix, float4 coalesced.
    #pragma unroll
    for (int kx = 0; kx < 8; kx++) {
        int idx4 = tid + kx*256;
        int c  = idx4 >> 5;        // 32 float4 per channel-row
        int p4 = idx4 & 31;
        float4 val = __ldg((const float4*)(src + (size_t)(b*C + c)*HW + pixBase + p4*4));
        *(float4*)&Xs[c*128 + p4*4] = val;
    }
    __syncthreads();

    const int tidx = tid & 31;     // pixel lane
    const int tidy = tid >> 5;     // out group (8 outs)
    const float* Wb = Wsrc + tidy*8*C;

    float acc[4][8];
    #pragma unroll
    for (int j = 0; j < 4; j++)
        #pragma unroll
        for (int i = 0; i < 8; i++) acc[j][i] = 0.f;

    #pragma unroll 4
    for (int c0 = 0; c0 < 64; c0 += 4) {
        float wreg[8][4];
        #pragma unroll
        for (int i = 0; i < 8; i++) {
            float4 t = __ldg((const float4*)(Wb + i*C + c0));
            wreg[i][0] = t.x; wreg[i][1] = t.y; wreg[i][2] = t.z; wreg[i][3] = t.w;
        }
        #pragma unroll
        for (int cc = 0; cc < 4; cc++) {
            #pragma unroll
            for (int j = 0; j < 4; j++) {
                float xv = Xs[(c0+cc)*128 + tidx + 32*j];
                #pragma unroll
                for (int i = 0; i < 8; i++)
                    acc[j][i] = fmaf(wreg[i][cc], xv, acc[j][i]);
            }
        }
    }

    // Store: per pixel, 8 consecutive floats (one full 32B sector) -> no waste.
    #pragma unroll
    for (int j = 0; j < 4; j++) {
        int pix = pixBase + tidx + 32*j;
        float4 a0 = make_float4(acc[j][0], acc[j][1], acc[j][2], acc[j][3]);
        float4 a1 = make_float4(acc[j][4], acc[j][5], acc[j][6], acc[j][7]);
        float* d = dst + (size_t)(b*HW + pix)*C + tidy*8;
        *(float4*)d       = a0;
        *(float4*)(d + 4) = a1;
    }
}

// ---------------------------------------------------------------------------
// Kernel 2: flow-guided attention, 6x6 shared-grid factorization.
// Warp per pixel. All 25 taps share one fractional offset -> 36 unique grid
// pixels. Pass A: s_j = q.K_j (36 dots). Logits = 2x2 blends of s. Softmax.
// Scatter probs into 36 grid coeffs c_j. Pass B: out = sum c_j * V_j.
// ---------------------------------------------------------------------------
__global__ __launch_bounds__(256) void attn_kernel(const float* __restrict__ flow,
                                                   float* __restrict__ attn_out)
{
    __shared__ float sP[8][NH][K2];
    __shared__ float sInv[8][NH];

    const int tid  = threadIdx.x;
    const int warp = tid >> 5;
    const int lane = tid & 31;

    const int b       = blockIdx.x / (HW/8);
    const int pixBase = (blockIdx.x % (HW/8)) * 8;
    const int pix     = pixBase + warp;
    const int y = pix >> 7;
    const int x = pix & 127;

    const float fx = flow[(b*2 + 0)*HW + pix];
    const float fy = flow[(b*2 + 1)*HW + pix];

    const float ax = (float)x + fx;
    const float ay = (float)y + fy;
    const float x0f = floorf(ax), y0f = floorf(ay);
    const int ix_base = (int)x0f - 2;
    const int iy_base = (int)y0f - 2;
    const float wx1 = ax - x0f, wx0 = 1.f - wx1;
    const float wy1 = ay - y0f, wy0 = 1.f - wy1;

    const float2* __restrict__ qp2 = (const float2*)g_qp;
    const float2* __restrict__ kp2 = (const float2*)g_kp;
    const float2* __restrict__ vp2 = (const float2*)g_vp;

    float2 qv = qp2[(size_t)(b*HW + pix)*32 + lane];
    const float scale = 0.25f;              // 1/sqrt(dk=16)
    qv.x *= scale; qv.y *= scale;

    const int head = lane >> 3;
    const size_t batchOff = (size_t)b*HW;

    // Pass A: 36 grid dots (per-head, replicated across the head's 8 lanes).
    float s[36];
    #pragma unroll
    for (int dy = 0; dy < 6; dy++) {
        int iy = iy_base + dy;
        bool okY = ((unsigned)iy < (unsigned)H);
        int iyc = min(max(iy, 0), H-1);
        #pragma unroll
        for (int dx = 0; dx < 6; dx++) {
            int ix = ix_base + dx;
            bool ok = okY && ((unsigned)ix < (unsigned)WW);
            int ixc = min(max(ix, 0), WW-1);
            float2 kv = __ldg(&kp2[(batchOff + iyc*WW + ixc)*32 + lane]);
            float d = qv.x*kv.x + qv.y*kv.y;
            d += __shfl_xor_sync(0xffffffffu, d, 1);
            d += __shfl_xor_sync(0xffffffffu, d, 2);
            d += __shfl_xor_sync(0xffffffffu, d, 4);
            s[dy*6 + dx] = ok ? d : 0.f;
        }
    }

    // Logits via 2x2 blends, then softmax over 25 taps.
    float p[25];
    float m = -1e30f;
    #pragma unroll
    for (int ty = 0; ty < 5; ty++) {
        #pragma unroll
        for (int tx = 0; tx < 5; tx++) {
            float l = wy0 * fmaf(wx0, s[ty*6+tx],     wx1 * s[ty*6+tx+1])
                    + wy1 * fmaf(wx0, s[(ty+1)*6+tx], wx1 * s[(ty+1)*6+tx+1]);
            p[ty*5 + tx] = l;
            m = fmaxf(m, l);
        }
    }
    float sum = 0.f;
    #pragma unroll
    for (int t = 0; t < K2; t++) { p[t] = __expf(p[t] - m); sum += p[t]; }
    const float inv = 1.f / sum;

    if ((lane & 7) == 0) {
        #pragma unroll
        for (int t = 0; t < K2; t++) sP[warp][head][t] = p[t];
        sInv[warp][head] = inv;
    }

    // Scatter tap probs into grid coefficients.
    float cg[36];
    #pragma unroll
    for (int j = 0; j < 36; j++) cg[j] = 0.f;
    const float w00 = wy0*wx0, w01 = wy0*wx1, w10 = wy1*wx0, w11 = wy1*wx1;
    #pragma unroll
    for (int ty = 0; ty < 5; ty++) {
        #pragma unroll
        for (int tx = 0; tx < 5; tx++) {
            float pt = p[ty*5 + tx];
            cg[ty*6 + tx]       = fmaf(pt, w00, cg[ty*6 + tx]);
            cg[ty*6 + tx+1]     = fmaf(pt, w01, cg[ty*6 + tx+1]);
            cg[(ty+1)*6 + tx]   = fmaf(pt, w10, cg[(ty+1)*6 + tx]);
            cg[(ty+1)*6 + tx+1] = fmaf(pt, w11, cg[(ty+1)*6 + tx+1]);
        }
    }

    // Pass B: V accumulation over the 36 grid pixels.
    float accx = 0.f, accy = 0.f;
    #pragma unroll
    for (int dy = 0; dy < 6; dy++) {
        int iy = iy_base + dy;
        bool okY = ((unsigned)iy < (unsigned)H);
        int iyc = min(max(iy, 0), H-1);
        #pragma unroll
        for (int dx = 0; dx < 6; dx++) {
            int ix = ix_base + dx;
            bool ok = okY && ((unsigned)ix < (unsigned)WW);
            int ixc = min(max(ix, 0), WW-1);
            float coef = ok ? cg[dy*6 + dx] * inv : 0.f;
            float2 vv = __ldg(&vp2[(batchOff + iyc*WW + ixc)*32 + lane]);
            accx = fmaf(coef, vv.x, accx);
            accy = fmaf(coef, vv.y, accy);
        }
    }

    ((float2*)g_mid)[(size_t)(b*HW + pix)*32 + lane] = make_float2(accx, accy);

    __syncthreads();

    // attn map [n, nh, k2, h, w]; 4*25*8 = 800 values per block, pixel-fastest.
    for (int i = tid; i < NH*K2*8; i += 256) {
        int pi = i & 7;
        int ht = i >> 3;
        int hh = ht / K2, t = ht % K2;
        float val = sP[pi][hh][t] * sInv[pi][hh];
        attn_out[((size_t)(b*NH + hh)*K2 + t)*HW + pixBase + pi] = val;
    }
}

// ---------------------------------------------------------------------------
// Kernel 3: final 1x1 conv, g_mid [n,hw,c] -> out [n,c,h,w].
// Block: 256 threads = 8 warps x 4 pixels = 32 pixels. Warp-cooperative:
// lane owns 2 output channels; x row distributed (lane holds ch 2l,2l+1),
// broadcast x via shuffle; W transposed in smem. Output transposed via smem.
// ---------------------------------------------------------------------------
__global__ __launch_bounds__(256) void conv_out_kernel(const float* __restrict__ Wfc,
                                                       float* __restrict__ out)
{
    __shared__ float Wt[64*66];   // Wt[c][o], pad 66
    __shared__ float O[64*33];    // O[o][pix], pad 33

    const int tid  = threadIdx.x;
    const int warp = tid >> 5;
    const int lane = tid & 31;

    const int pixAll  = blockIdx.x * 32;
    const int b       = pixAll / HW;
    const int pixBase = pixAll % HW;

    // Stage W transposed: Wfc[o*64+c] -> Wt[c*66+o]  (~2-way conflict, once).
    for (int i = tid; i < C*C; i += 256)
        Wt[(i & 63)*66 + (i >> 6)] = Wfc[i];
    __syncthreads();

    const float2* __restrict__ mid2 = (const float2*)g_mid;
    const int pixL = warp*4;

    float2 xl[4];
    #pragma unroll
    for (int j = 0; j < 4; j++)
        xl[j] = mid2[(size_t)(b*HW + pixBase + pixL + j)*32 + lane];

    float2 acc[4];
    #pragma unroll
    for (int j = 0; j < 4; j++) acc[j] = make_float2(0.f, 0.f);

    #pragma unroll
    for (int c = 0; c < 64; c++) {
        float2 wv = *(const float2*)&Wt[c*66 + lane*2];
        #pragma unroll
        for (int j = 0; j < 4; j++) {
            float xls = (c & 1) ? xl[j].y : xl[j].x;
            float xc  = __shfl_sync(0xffffffffu, xls, c >> 1);
            acc[j].x = fmaf(wv.x, xc, acc[j].x);
            acc[j].y = fmaf(wv.y, xc, acc[j].y);
        }
    }

    // Stage output transpose in smem.
    #pragma unroll
    for (int j = 0; j < 4; j++) {
        O[(2*lane    )*33 + pixL + j] = acc[j].x;
        O[(2*lane + 1)*33 + pixL + j] = acc[j].y;
    }
    __syncthreads();

    // Coalesced copy to global [n,c,h,w].
    #pragma unroll
    for (int i = tid; i < C*32; i += 256) {
        int o = i >> 5, pp = i & 31;
        out[(size_t)(b*C + o)*HW + pixBase + pp] = O[o*33 + pp];
    }
}

// ---------------------------------------------------------------------------
extern "C" void kernel_launch(void* const* d_in, const int* in_sizes, int n_in,
                              void* d_out, int out_size)
{
    const float* q    = (const float*)d_in[0];
    const float* k    = (const float*)d_in[1];
    const float* v    = (const float*)d_in[2];
    const float* flow = (const float*)d_in[3];
    const float* Wq   = (const float*)d_in[4];
    const float* Wk   = (const float*)d_in[5];
    const float* Wv   = (const float*)d_in[6];
    const float* Wfc  = (const float*)d_in[7];

    float* out  = (float*)d_out;              // [n, c, h, w]
    float* attn = out + NB*C*HW;              // [n, nh, k2, h, w]

    dim3 g1(NB*HW/128, 3);
    conv_in_kernel<<<g1, 256>>>(q, k, v, Wq, Wk, Wv);
    attn_kernel<<<NB*HW/8, 256>>>(flow, attn);
    conv_out_kernel<<<NB*HW/32, 256>>>(Wfc, out);
}